// round 1
// baseline (speedup 1.0000x reference)
#include <cuda_runtime.h>
#include <cstdint>

// Problem constants
#define B_DIM   8192
#define IN_DIM  256
#define OUT_DIM 256
#define MV      8

// Tiling
#define B_TILE  64
#define I_TILE  64
#define KJ      8           // j's per shared-memory chunk
#define NCHUNK  (IN_DIM / KJ)

typedef unsigned long long u64;

// ---- packed f32x2 helpers (FFMA2 path; ptxas never emits these from C++) ----
__device__ __forceinline__ u64 pack2(float lo, float hi) {
    u64 r; asm("mov.b64 %0, {%1, %2};" : "=l"(r) : "f"(lo), "f"(hi)); return r;
}
__device__ __forceinline__ u64 fma2(u64 a, u64 b, u64 c) {
    u64 d; asm("fma.rn.f32x2 %0, %1, %2, %3;" : "=l"(d) : "l"(a), "l"(b), "l"(c)); return d;
}
__device__ __forceinline__ void unpack2(u64 v, float& lo, float& hi) {
    asm("mov.b64 {%0, %1}, %2;" : "=f"(lo), "=f"(hi) : "l"(v));
}

// y[b,i,0] = bias[i,0] + sum_j x0*w0 + x1*w1 + x2*w2
// y[b,i,4] = bias[i,4] + sum_j x1*w2 - x2*w1 + x4*w0
// y[b,i,k] = bias[i,k]  (k != 0,4)
__global__ void __launch_bounds__(256, 2)
ga_mv_kernel(const float* __restrict__ x,
             const float* __restrict__ w,
             const float* __restrict__ bias,
             float* __restrict__ out)
{
    // Xs[j][b][5] pairs: {x0,x0},{x1,x1},{x2,x2},{x4,x4},{-x2,-x2}
    __shared__ u64   Xs[KJ][B_TILE][5];          // 20 KB
    __shared__ float Ws[3][KJ][I_TILE];          // 6 KB (w0,w1,w2 SoA, i contiguous)

    const int tid   = threadIdx.x;
    const int tx    = tid & 15;       // 16 i-groups
    const int ty    = tid >> 4;       // 16 b-groups
    const int i0    = tx * 4;         // local i base (4 i's = 2 pairs)
    const int brow  = ty * 4;         // local b base (4 b's)
    const int bBase = blockIdx.x * B_TILE;
    const int iBase = blockIdx.y * I_TILE;

    u64 a0[4][2], a4[4][2];
    #pragma unroll
    for (int bb = 0; bb < 4; bb++) {
        a0[bb][0] = 0ull; a0[bb][1] = 0ull;
        a4[bb][0] = 0ull; a4[bb][1] = 0ull;
    }

    for (int c = 0; c < NCHUNK; c++) {
        const int j0 = c * KJ;

        // ---- stage X: 64 b x 8 j, 2 (b,j) cells per thread; 32B contiguous per cell
        #pragma unroll
        for (int t = 0; t < 2; t++) {
            int p = tid + t * 256;
            int j = p & (KJ - 1);
            int b = p >> 3;
            const float4* src = (const float4*)(x + ((size_t)(bBase + b) * IN_DIM + (j0 + j)) * MV);
            float4 lo = src[0];
            float4 hi = src[1];
            u64* dst = Xs[j][b];
            dst[0] = pack2(lo.x,  lo.x);    // x0
            dst[1] = pack2(lo.y,  lo.y);    // x1
            dst[2] = pack2(lo.z,  lo.z);    // x2
            dst[3] = pack2(hi.x,  hi.x);    // x4
            dst[4] = pack2(-lo.z, -lo.z);   // -x2
        }

        // ---- stage W: 8 j x 64 i, 2 (j,i) cells per thread
        #pragma unroll
        for (int t = 0; t < 2; t++) {
            int p = tid + t * 256;
            int i = p & (I_TILE - 1);
            int j = p >> 6;
            float4 wq = *(const float4*)(w + ((size_t)(j0 + j) * OUT_DIM + (iBase + i)) * MV);
            Ws[0][j][i] = wq.x;
            Ws[1][j][i] = wq.y;
            Ws[2][j][i] = wq.z;
        }

        __syncthreads();

        // ---- compute: 8 j x 4 b x 2 i-pairs x 6 fma2
        #pragma unroll
        for (int j = 0; j < KJ; j++) {
            u64 w0p0 = *(const u64*)&Ws[0][j][i0];
            u64 w0p1 = *(const u64*)&Ws[0][j][i0 + 2];
            u64 w1p0 = *(const u64*)&Ws[1][j][i0];
            u64 w1p1 = *(const u64*)&Ws[1][j][i0 + 2];
            u64 w2p0 = *(const u64*)&Ws[2][j][i0];
            u64 w2p1 = *(const u64*)&Ws[2][j][i0 + 2];
            #pragma unroll
            for (int bb = 0; bb < 4; bb++) {
                const u64* xp = Xs[j][brow + bb];
                u64 x0  = xp[0];
                u64 x1  = xp[1];
                u64 x2  = xp[2];
                u64 x4  = xp[3];
                u64 x2n = xp[4];

                a0[bb][0] = fma2(x0,  w0p0, a0[bb][0]);
                a0[bb][0] = fma2(x1,  w1p0, a0[bb][0]);
                a0[bb][0] = fma2(x2,  w2p0, a0[bb][0]);
                a0[bb][1] = fma2(x0,  w0p1, a0[bb][1]);
                a0[bb][1] = fma2(x1,  w1p1, a0[bb][1]);
                a0[bb][1] = fma2(x2,  w2p1, a0[bb][1]);

                a4[bb][0] = fma2(x1,  w2p0, a4[bb][0]);
                a4[bb][0] = fma2(x2n, w1p0, a4[bb][0]);
                a4[bb][0] = fma2(x4,  w0p0, a4[bb][0]);
                a4[bb][1] = fma2(x1,  w2p1, a4[bb][1]);
                a4[bb][1] = fma2(x2n, w1p1, a4[bb][1]);
                a4[bb][1] = fma2(x4,  w0p1, a4[bb][1]);
            }
        }
        __syncthreads();
    }

    // ---- epilogue: write all 8 components (bias + c0/c4)
    #pragma unroll
    for (int bb = 0; bb < 4; bb++) {
        const int bg = bBase + brow + bb;
        #pragma unroll
        for (int pp = 0; pp < 2; pp++) {
            float c0lo, c0hi, c4lo, c4hi;
            unpack2(a0[bb][pp], c0lo, c0hi);
            unpack2(a4[bb][pp], c4lo, c4hi);
            #pragma unroll
            for (int q = 0; q < 2; q++) {
                const int ig = iBase + i0 + pp * 2 + q;
                float c0 = q ? c0hi : c0lo;
                float c4 = q ? c4hi : c4lo;
                float4 blo = *(const float4*)(bias + (size_t)ig * MV);
                float4 bhi = *(const float4*)(bias + (size_t)ig * MV + 4);
                blo.x += c0;
                bhi.x += c4;
                float4* o = (float4*)(out + ((size_t)bg * OUT_DIM + ig) * MV);
                o[0] = blo;
                o[1] = bhi;
            }
        }
    }
}

extern "C" void kernel_launch(void* const* d_in, const int* in_sizes, int n_in,
                              void* d_out, int out_size)
{
    const float* x    = (const float*)d_in[0];   // (8192, 256, 8)
    const float* w    = (const float*)d_in[1];   // (256, 256, 8)
    const float* bias = (const float*)d_in[2];   // (256, 8)
    float* out        = (float*)d_out;           // (8192, 256, 8)

    dim3 grid(B_DIM / B_TILE, OUT_DIM / I_TILE); // (128, 4)
    dim3 block(256);
    ga_mv_kernel<<<grid, block>>>(x, w, bias, out);
}

// round 2
// speedup vs baseline: 1.3648x; 1.3648x over previous
#include <cuda_runtime.h>
#include <cstdint>

// Problem constants
#define B_DIM   8192
#define IN_DIM  256
#define OUT_DIM 256
#define MV      8

// Tiling
#define B_TILE   64          // 32 b-pairs
#define BP_TILE  32
#define I_TILE   64
#define KJ       8
#define NCHUNK   (IN_DIM / KJ)

typedef unsigned long long u64;

__device__ __forceinline__ u64 pack2(float lo, float hi) {
    u64 r; asm("mov.b64 %0, {%1, %2};" : "=l"(r) : "f"(lo), "f"(hi)); return r;
}
__device__ __forceinline__ u64 fma2(u64 a, u64 b, u64 c) {
    u64 d; asm("fma.rn.f32x2 %0, %1, %2, %3;" : "=l"(d) : "l"(a), "l"(b), "l"(c)); return d;
}
__device__ __forceinline__ void unpack2(u64 v, float& lo, float& hi) {
    asm("mov.b64 {%0, %1}, %2;" : "=f"(lo), "=f"(hi) : "l"(v));
}

// y[b,i,0] = bias[i,0] + sum_j x0*w0 + x1*w1 + x2*w2
// y[b,i,4] = bias[i,4] + sum_j x1*w2 - x2*w1 + x4*w0
__global__ void __launch_bounds__(256, 2)
ga_mv_kernel(const float* __restrict__ x,
             const float* __restrict__ w,
             const float* __restrict__ bias,
             float* __restrict__ out)
{
    // X as b-pairs: lane0 = b even, lane1 = b odd. comp: x0,x1,x2,x4,-x2
    __shared__ u64 Xs[KJ][5][BP_TILE + 1];   // ~10.5 KB  (+1 pad vs staging conflicts)
    __shared__ u64 Ws[3][KJ][I_TILE];        // 12 KB, duplicated {w,w}

    const int tid   = threadIdx.x;
    const int tx    = tid & 15;          // i-group: i = tx + 16q, q=0..3  (conflict-free LDS)
    const int ty    = tid >> 4;          // b-group: bpairs bp0, bp0+1
    const int bp0   = ty * 2;
    const int bBase = blockIdx.x * B_TILE;
    const int iBase = blockIdx.y * I_TILE;

    u64 a0[2][4], a4[2][4];
    #pragma unroll
    for (int r = 0; r < 2; r++)
        #pragma unroll
        for (int q = 0; q < 4; q++) { a0[r][q] = 0ull; a4[r][q] = 0ull; }

    for (int c = 0; c < NCHUNK; c++) {
        const int j0 = c * KJ;

        // ---- stage X: one (bp, j) cell per thread; j fastest -> coalesced LDG
        {
            const int j  = tid & (KJ - 1);
            const int bp = tid >> 3;
            const float* rowA = x + ((size_t)(bBase + 2 * bp) * IN_DIM + (j0 + j)) * MV;
            const float* rowB = rowA + (size_t)IN_DIM * MV;
            float4 A  = *(const float4*)rowA;
            float  A4 = rowA[4];
            float4 Bv = *(const float4*)rowB;
            float  B4 = rowB[4];
            Xs[j][0][bp] = pack2(A.x,  Bv.x);     // x0
            Xs[j][1][bp] = pack2(A.y,  Bv.y);     // x1
            Xs[j][2][bp] = pack2(A.z,  Bv.z);     // x2
            Xs[j][3][bp] = pack2(A4,   B4);       // x4
            Xs[j][4][bp] = pack2(-A.z, -Bv.z);    // -x2
        }

        // ---- stage W: 2 (j, i) cells per thread; i fastest -> coalesced LDG
        #pragma unroll
        for (int t = 0; t < 2; t++) {
            const int p = tid + t * 256;
            const int i = p & (I_TILE - 1);
            const int j = p >> 6;
            float4 wq = *(const float4*)(w + ((size_t)(j0 + j) * OUT_DIM + (iBase + i)) * MV);
            Ws[0][j][i] = pack2(wq.x, wq.x);
            Ws[1][j][i] = pack2(wq.y, wq.y);
            Ws[2][j][i] = pack2(wq.z, wq.z);
        }

        __syncthreads();

        // ---- compute: 8 j x (12 W-LDS + 2 bpairs x (5 X-LDS + 24 fma2))
        #pragma unroll
        for (int j = 0; j < KJ; j++) {
            u64 W0[4], W1[4], W2[4];
            #pragma unroll
            for (int q = 0; q < 4; q++) {
                W0[q] = Ws[0][j][tx + 16 * q];
                W1[q] = Ws[1][j][tx + 16 * q];
                W2[q] = Ws[2][j][tx + 16 * q];
            }
            #pragma unroll
            for (int r = 0; r < 2; r++) {
                const int bp = bp0 + r;
                u64 x0  = Xs[j][0][bp];
                u64 x1  = Xs[j][1][bp];
                u64 x2  = Xs[j][2][bp];
                u64 x4  = Xs[j][3][bp];
                u64 x2n = Xs[j][4][bp];
                #pragma unroll
                for (int q = 0; q < 4; q++) {
                    a0[r][q] = fma2(x0,  W0[q], a0[r][q]);
                    a0[r][q] = fma2(x1,  W1[q], a0[r][q]);
                    a0[r][q] = fma2(x2,  W2[q], a0[r][q]);
                    a4[r][q] = fma2(x1,  W2[q], a4[r][q]);
                    a4[r][q] = fma2(x2n, W1[q], a4[r][q]);
                    a4[r][q] = fma2(x4,  W0[q], a4[r][q]);
                }
            }
        }
        __syncthreads();
    }

    // ---- epilogue: full 8-component rows (bias + c0/c4 into slots 0 and 4)
    #pragma unroll
    for (int q = 0; q < 4; q++) {
        const int ig = iBase + tx + 16 * q;
        float4 blo = *(const float4*)(bias + (size_t)ig * MV);
        float4 bhi = *(const float4*)(bias + (size_t)ig * MV + 4);
        #pragma unroll
        for (int r = 0; r < 2; r++) {
            float c0e, c0o, c4e, c4o;
            unpack2(a0[r][q], c0e, c0o);
            unpack2(a4[r][q], c4e, c4o);
            const int bE = bBase + 2 * (bp0 + r);

            float4 v0 = blo; v0.x += c0e;
            float4 v1 = bhi; v1.x += c4e;
            float4* o = (float4*)(out + ((size_t)bE * OUT_DIM + ig) * MV);
            o[0] = v0; o[1] = v1;

            v0 = blo; v0.x += c0o;
            v1 = bhi; v1.x += c4o;
            o = (float4*)(out + ((size_t)(bE + 1) * OUT_DIM + ig) * MV);
            o[0] = v0; o[1] = v1;
        }
    }
}

extern "C" void kernel_launch(void* const* d_in, const int* in_sizes, int n_in,
                              void* d_out, int out_size)
{
    const float* x    = (const float*)d_in[0];   // (8192, 256, 8)
    const float* w    = (const float*)d_in[1];   // (256, 256, 8)
    const float* bias = (const float*)d_in[2];   // (256, 8)
    float* out        = (float*)d_out;           // (8192, 256, 8)

    dim3 grid(B_DIM / B_TILE, OUT_DIM / I_TILE); // (128, 4)
    dim3 block(256);
    ga_mv_kernel<<<grid, block>>>(x, w, bias, out);
}

// round 4
// speedup vs baseline: 1.5651x; 1.1467x over previous
#include <cuda_runtime.h>
#include <cstdint>

// Problem constants
#define B_DIM   8192
#define IN_DIM  256
#define OUT_DIM 256
#define MV      8

// Tiling
#define MT      128          // b rows per CTA (64 b-pairs)
#define BP      64
#define IT      64           // i per CTA
#define KJ      8            // j per chunk
#define NCH     (IN_DIM / KJ)   // 32
#define XPAD    66           // bp-dim pad: 16B-aligned rows, low STS conflicts

typedef unsigned long long u64;

struct __align__(16) Smem {
    u64 X[2][KJ][5][XPAD];   // comps: x0,x1,x2,x4,-x2 as {b even, b odd} pairs
    u64 W[2][3][KJ][IT];     // w0,w1,w2 duplicated {w,w}
};

__device__ __forceinline__ u64 pack2(float lo, float hi) {
    u64 r; asm("mov.b64 %0, {%1, %2};" : "=l"(r) : "f"(lo), "f"(hi)); return r;
}
__device__ __forceinline__ u64 fma2(u64 a, u64 b, u64 c) {
    u64 d; asm("fma.rn.f32x2 %0, %1, %2, %3;" : "=l"(d) : "l"(a), "l"(b), "l"(c)); return d;
}
__device__ __forceinline__ void unpack2(u64 v, float& lo, float& hi) {
    asm("mov.b64 {%0, %1}, %2;" : "=f"(lo), "=f"(hi) : "l"(v));
}

// y[b,i,0] = bias[i,0] + sum_j x0*w0 + x1*w1 + x2*w2
// y[b,i,4] = bias[i,4] + sum_j x1*w2 - x2*w1 + x4*w0
__global__ void __launch_bounds__(256, 2)
ga_mv_kernel(const float* __restrict__ x,
             const float* __restrict__ w,
             const float* __restrict__ bias,
             float* __restrict__ out)
{
    extern __shared__ char smraw[];
    Smem* sm = (Smem*)smraw;

    const int tid   = threadIdx.x;
    const int tx    = tid & 15;        // i = tx + 16q (broadcast-friendly W LDS)
    const int ty    = tid >> 4;        // bp0 = ty*4 -> 4 bpairs per thread
    const int bp0   = ty * 4;
    const int bBase = blockIdx.x * MT;
    const int iBase = blockIdx.y * IT;

    // staging mappings (both cells share j / i; second cell offsets bp/jj)
    const int xj  = tid & 7;           // X: j
    const int xbp = tid >> 3;          // X: bp (cell 1: +32)
    const int wi  = tid & 63;          // W: i
    const int wjj = tid >> 6;          // W: j (cell 1: +4)

    // prefetch registers
    float xA[2][4], xB[2][4];          // comps {0,1,2,4} of even/odd row, 2 cells
    float wv[2][3];

    u64 a0[4][4], a4[4][4];
    #pragma unroll
    for (int r = 0; r < 4; r++)
        #pragma unroll
        for (int q = 0; q < 4; q++) { a0[r][q] = 0ull; a4[r][q] = 0ull; }

    auto LOAD = [&](int c) {
        const int j0 = c * KJ;
        #pragma unroll
        for (int t = 0; t < 2; t++) {
            const float* ra = x + ((size_t)(bBase + 2 * (xbp + 32 * t)) * IN_DIM + (j0 + xj)) * MV;
            const float* rb = ra + (size_t)IN_DIM * MV;
            float4 a = *(const float4*)ra;
            xA[t][0] = a.x; xA[t][1] = a.y; xA[t][2] = a.z; xA[t][3] = ra[4];
            float4 b = *(const float4*)rb;
            xB[t][0] = b.x; xB[t][1] = b.y; xB[t][2] = b.z; xB[t][3] = rb[4];
        }
        #pragma unroll
        for (int t = 0; t < 2; t++) {
            const float* wr = w + ((size_t)(j0 + wjj + 4 * t) * OUT_DIM + (iBase + wi)) * MV;
            float4 q = *(const float4*)wr;
            wv[t][0] = q.x; wv[t][1] = q.y; wv[t][2] = q.z;
        }
    };

    auto STORE = [&](int buf) {
        #pragma unroll
        for (int t = 0; t < 2; t++) {
            const int bp = xbp + 32 * t;
            sm->X[buf][xj][0][bp] = pack2(xA[t][0],  xB[t][0]);
            sm->X[buf][xj][1][bp] = pack2(xA[t][1],  xB[t][1]);
            sm->X[buf][xj][2][bp] = pack2(xA[t][2],  xB[t][2]);
            sm->X[buf][xj][3][bp] = pack2(xA[t][3],  xB[t][3]);
            sm->X[buf][xj][4][bp] = pack2(-xA[t][2], -xB[t][2]);
        }
        #pragma unroll
        for (int t = 0; t < 2; t++) {
            const int jj = wjj + 4 * t;
            sm->W[buf][0][jj][wi] = pack2(wv[t][0], wv[t][0]);
            sm->W[buf][1][jj][wi] = pack2(wv[t][1], wv[t][1]);
            sm->W[buf][2][jj][wi] = pack2(wv[t][2], wv[t][2]);
        }
    };

    LOAD(0);
    STORE(0);
    __syncthreads();

    for (int c = 0; c < NCH; c++) {
        const int buf = c & 1;
        if (c + 1 < NCH) LOAD(c + 1);

        #pragma unroll
        for (int j = 0; j < KJ; j++) {
            u64 W0[4], W1[4], W2[4];
            #pragma unroll
            for (int q = 0; q < 4; q++) {
                W0[q] = sm->W[buf][0][j][tx + 16 * q];
                W1[q] = sm->W[buf][1][j][tx + 16 * q];
                W2[q] = sm->W[buf][2][j][tx + 16 * q];
            }
            #pragma unroll
            for (int h = 0; h < 2; h++) {
                // LDS.128: two adjacent bpairs per comp
                ulonglong2 v0 = *(const ulonglong2*)&sm->X[buf][j][0][bp0 + 2 * h];
                ulonglong2 v1 = *(const ulonglong2*)&sm->X[buf][j][1][bp0 + 2 * h];
                ulonglong2 v2 = *(const ulonglong2*)&sm->X[buf][j][2][bp0 + 2 * h];
                ulonglong2 v3 = *(const ulonglong2*)&sm->X[buf][j][3][bp0 + 2 * h];
                ulonglong2 v4 = *(const ulonglong2*)&sm->X[buf][j][4][bp0 + 2 * h];
                #pragma unroll
                for (int rr = 0; rr < 2; rr++) {
                    const int r = 2 * h + rr;
                    const u64 x0  = rr ? v0.y : v0.x;
                    const u64 x1  = rr ? v1.y : v1.x;
                    const u64 x2  = rr ? v2.y : v2.x;
                    const u64 x4  = rr ? v3.y : v3.x;
                    const u64 x2n = rr ? v4.y : v4.x;
                    #pragma unroll
                    for (int q = 0; q < 4; q++) {
                        a0[r][q] = fma2(x0,  W0[q], a0[r][q]);
                        a0[r][q] = fma2(x1,  W1[q], a0[r][q]);
                        a0[r][q] = fma2(x2,  W2[q], a0[r][q]);
                        a4[r][q] = fma2(x1,  W2[q], a4[r][q]);
                        a4[r][q] = fma2(x2n, W1[q], a4[r][q]);
                        a4[r][q] = fma2(x4,  W0[q], a4[r][q]);
                    }
                }
            }
        }

        if (c + 1 < NCH) STORE((c + 1) & 1);
        __syncthreads();
    }

    // ---- epilogue: bias + c0/c4 into slots 0 and 4
    #pragma unroll
    for (int q = 0; q < 4; q++) {
        const int ig = iBase + tx + 16 * q;
        float4 blo = *(const float4*)(bias + (size_t)ig * MV);
        float4 bhi = *(const float4*)(bias + (size_t)ig * MV + 4);
        #pragma unroll
        for (int r = 0; r < 4; r++) {
            float c0e, c0o, c4e, c4o;
            unpack2(a0[r][q], c0e, c0o);
            unpack2(a4[r][q], c4e, c4o);
            const int bE = bBase + 2 * (bp0 + r);

            float4 v0 = blo; v0.x += c0e;
            float4 v1 = bhi; v1.x += c4e;
            float4* o = (float4*)(out + ((size_t)bE * OUT_DIM + ig) * MV);
            o[0] = v0; o[1] = v1;

            v0 = blo; v0.x += c0o;
            v1 = bhi; v1.x += c4o;
            o = (float4*)(out + ((size_t)(bE + 1) * OUT_DIM + ig) * MV);
            o[0] = v0; o[1] = v1;
        }
    }
}

extern "C" void kernel_launch(void* const* d_in, const int* in_sizes, int n_in,
                              void* d_out, int out_size)
{
    const float* x    = (const float*)d_in[0];   // (8192, 256, 8)
    const float* w    = (const float*)d_in[1];   // (256, 256, 8)
    const float* bias = (const float*)d_in[2];   // (256, 8)
    float* out        = (float*)d_out;           // (8192, 256, 8)

    static int attr_set = 0;
    if (!attr_set) {
        cudaFuncSetAttribute(ga_mv_kernel, cudaFuncAttributeMaxDynamicSharedMemorySize,
                             (int)sizeof(Smem));
        attr_set = 1;
    }

    dim3 grid(B_DIM / MT, OUT_DIM / IT);         // (64, 4) = 256 CTAs
    ga_mv_kernel<<<grid, 256, sizeof(Smem)>>>(x, w, bias, out);
}